// round 15
// baseline (speedup 1.0000x reference)
#include <cuda_runtime.h>
#include <cstdint>

// Problem constants (B=2, C=1, D=128, H=256, W=256)
#define NVOL   2
#define DD     128
#define HH     256
#define WW     256
#define NB     (NVOL*DD*HH*WW)      // 16,777,216 voxels
#define WPR    (WW/32)              // 8 packed words per row
#define NWORDS (NVOL*DD*HH*WPR)     // 524,288 words (2 MB)
#define PW     10.0

// pass1: 4096 blocks x 256 thr = 1,048,576 threads -> 4 quads/thread
#define P1_BLOCKS  4096
#define P1_THREADS 256
#define P1_TOTAL   (P1_BLOCKS*P1_THREADS)

// merged dilation kernel: block = (v, y-group of 8, wx); full z inside block
#define DM_THREADS 128
#define DM_BLOCKS  (NVOL * 32 * 8)        // 512 blocks
#define ZSTRIDE    132                    // padded z-stride in smem tile

// Scratch (allocation-free __device__ globals; zero-initialized at load)
__device__ unsigned int g_mask[NWORDS];
__device__ double g_base;      // sum |t-i| over all voxels
__device__ double g_corr;      // sum |t-i| over NOT-dilated voxels
__device__ unsigned int g_bcount;

// ---------------------------------------------------------------------------
// Pass 1: single streaming read of input+target (128 MB).
// Emits base = sum|t-i| and packed support mask (0 < t < 1).
// ---------------------------------------------------------------------------
__global__ void __launch_bounds__(P1_THREADS) pass1_kernel(
        const float4* __restrict__ inp,
        const float4* __restrict__ tgt) {
    int tid = blockIdx.x * blockDim.x + threadIdx.x;
    float base = 0.0f;

    float4 a[4], b[4];
    #pragma unroll
    for (int k = 0; k < 4; ++k) {
        int i = tid + k * P1_TOTAL;
        a[k] = __ldcs(inp + i);
        b[k] = __ldcs(tgt + i);
    }
    #pragma unroll
    for (int k = 0; k < 4; ++k) {
        int i = tid + k * P1_TOTAL;
        float dx = fabsf(b[k].x - a[k].x);
        float dy = fabsf(b[k].y - a[k].y);
        float dz = fabsf(b[k].z - a[k].z);
        float dw = fabsf(b[k].w - a[k].w);
        base += (dx + dy) + (dz + dw);

        unsigned nib =
            (unsigned)(b[k].x > 0.0f && b[k].x < 1.0f)
          | ((unsigned)(b[k].y > 0.0f && b[k].y < 1.0f) << 1)
          | ((unsigned)(b[k].z > 0.0f && b[k].z < 1.0f) << 2)
          | ((unsigned)(b[k].w > 0.0f && b[k].w < 1.0f) << 3);
        // 8 consecutive threads' nibbles -> one 32-bit word
        unsigned p  = nib | (__shfl_down_sync(0xFFFFFFFFu, nib, 1) << 4);
        unsigned p2 = p   | (__shfl_down_sync(0xFFFFFFFFu, p,   2) << 8);
        unsigned w  = p2  | (__shfl_down_sync(0xFFFFFFFFu, p2,  4) << 16);
        if ((threadIdx.x & 7) == 0) g_mask[i >> 3] = w;
    }

    #pragma unroll
    for (int off = 16; off > 0; off >>= 1)
        base += __shfl_down_sync(0xFFFFFFFFu, base, off);
    __shared__ float ws[P1_THREADS / 32];
    int lane = threadIdx.x & 31, wid = threadIdx.x >> 5;
    if (lane == 0) ws[wid] = base;
    __syncthreads();
    if (wid == 0) {
        float s = (lane < P1_THREADS / 32) ? ws[lane] : 0.0f;
        #pragma unroll
        for (int off = 4; off > 0; off >>= 1)
            s += __shfl_down_sync(0xFFFFFFFFu, s, off);
        if (lane == 0) atomicAdd(&g_base, (double)s);
    }
}

// horizontal (x) dilation by +-3 bits across word boundaries
__device__ __forceinline__ unsigned hdil3(unsigned prev, unsigned cur, unsigned next) {
    unsigned r = cur;
    r |= __funnelshift_l(prev, cur, 1);
    r |= __funnelshift_l(prev, cur, 2);
    r |= __funnelshift_l(prev, cur, 3);
    r |= __funnelshift_r(cur, next, 1);
    r |= __funnelshift_r(cur, next, 2);
    r |= __funnelshift_r(cur, next, 3);
    return r;
}

// sliding OR of width 7 over win[0..13] -> out[0..7] using suffix/prefix split
__device__ __forceinline__ void slide_or7(const unsigned* win, unsigned* out) {
    unsigned suf[7], pre[7];
    suf[6] = win[6];
    #pragma unroll
    for (int i = 5; i >= 0; --i) suf[i] = win[i] | suf[i + 1];
    pre[0] = win[7];
    #pragma unroll
    for (int j = 1; j < 7; ++j) pre[j] = pre[j - 1] | win[7 + j];
    out[0] = suf[0];
    #pragma unroll
    for (int k = 1; k < 7; ++k) out[k] = suf[k] | pre[k - 1];
    out[7] = pre[6];                     // window lies entirely in prefix side
}

// ---------------------------------------------------------------------------
// Merged dilation: block = (v, yg of 8 rows, wx); full z in smem.
//   Phase A (thread = z): xy-dilation for 8 y's -> smem tile [y][z]
//   Phase B (thread = (y, z-chunk of 8)): z-dilation from smem, complement,
//            gather |t-i| for unweighted voxels, reduce, finalize.
//   loss = 11*base - 10*corr ; out = loss/NB written by the last block.
// No grid barrier, no g_tmp round-trip, one launch instead of two.
// ---------------------------------------------------------------------------
__global__ void __launch_bounds__(DM_THREADS) dilate_merged_kernel(
        const float* __restrict__ inp,
        const float* __restrict__ tgt,
        float* __restrict__ out) {
    cudaGridDependencySynchronize();     // PDL: wait for pass1 completion
    __shared__ unsigned syx[8 * ZSTRIDE];   // [y][z], padded stride

    int b  = blockIdx.x;
    int wx = b & 7;
    int yg = (b >> 3) & 31;
    int v  = b >> 8;
    int tid = threadIdx.x;

    // ---- Phase A: xy dilation at z = tid for 8 y outputs ----
    {
        int z = tid;
        int zbase = ((v << 7) + z) << 11;          // word base of (v,z) slice
        unsigned hr[14];
        #pragma unroll
        for (int r = 0; r < 14; ++r) {
            int yy = (yg << 3) - 3 + r;
            unsigned cur = 0u, prev = 0u, next = 0u;
            if ((unsigned)yy < HH) {
                int base = zbase + (yy << 3);
                cur  = g_mask[base + wx];
                prev = (wx > 0) ? g_mask[base + wx - 1] : 0u;
                next = (wx < 7) ? g_mask[base + wx + 1] : 0u;
            }
            hr[r] = hdil3(prev, cur, next);
        }
        unsigned outw[8];
        slide_or7(hr, outw);
        #pragma unroll
        for (int k = 0; k < 8; ++k)
            syx[k * ZSTRIDE + z] = outw[k];
    }
    __syncthreads();

    // ---- Phase B: z dilation + complement correction ----
    float corr = 0.0f;
    {
        int y  = tid >> 4;                 // 0..7
        int z0 = (tid & 15) << 3;          // 0..120
        unsigned c[14];
        #pragma unroll
        for (int r = 0; r < 14; ++r) {
            int zz = z0 - 3 + r;
            c[r] = ((unsigned)zz < DD) ? syx[y * ZSTRIDE + zz] : 0u;
        }
        unsigned res[8];
        slide_or7(c, res);

        int ygl = (yg << 3) + y;           // global y row
        #pragma unroll
        for (int k = 0; k < 8; ++k) {
            unsigned miss = ~res[k];       // unweighted voxels
            if (miss) {
                int z = z0 + k;
                int gword = (((v << 7) + z) << 11) + (ygl << 3) + wx;
                int vox0 = gword << 5;
                do {
                    int bit = __ffs(miss) - 1;
                    miss &= miss - 1u;
                    int i = vox0 + bit;
                    corr += fabsf(tgt[i] - inp[i]);
                } while (miss);
            }
        }
    }

    // ---- reduce + finalize ----
    #pragma unroll
    for (int off = 16; off > 0; off >>= 1)
        corr += __shfl_down_sync(0xFFFFFFFFu, corr, off);
    __shared__ float ws[DM_THREADS / 32];
    int lane = tid & 31, wid = tid >> 5;
    if (lane == 0) ws[wid] = corr;
    __syncthreads();
    if (wid == 0) {
        float s = (lane < DM_THREADS / 32) ? ws[lane] : 0.0f;
        #pragma unroll
        for (int off = 2; off > 0; off >>= 1)
            s += __shfl_down_sync(0xFFFFFFFFu, s, off);
        if (lane == 0) {
            atomicAdd(&g_corr, (double)s);
            __threadfence();
            unsigned prev = atomicAdd(&g_bcount, 1u);
            if (prev == gridDim.x - 1) {
                double total = (1.0 + PW) * g_base - PW * g_corr;
                out[0] = (float)(total / (double)NB);
                g_base = 0.0;        // reset for next graph replay
                g_corr = 0.0;
                g_bcount = 0u;
            }
        }
    }
}

extern "C" void kernel_launch(void* const* d_in, const int* in_sizes, int n_in,
                              void* d_out, int out_size) {
    const float* inp = (const float*)d_in[0];
    const float* tgt = (const float*)d_in[1];
    float* out = (float*)d_out;

    pass1_kernel<<<P1_BLOCKS, P1_THREADS>>>((const float4*)inp, (const float4*)tgt);

    // Merged dilation with programmatic stream serialization: launch/ramp
    // overlaps pass1; cudaGridDependencySynchronize() provides the data
    // dependency. Default (kernel-end) trigger — early trigger measured
    // harmful for the BW-bound pass1 (R13).
    cudaLaunchAttribute attrs[1];
    attrs[0].id = cudaLaunchAttributeProgrammaticStreamSerialization;
    attrs[0].val.programmaticStreamSerializationAllowed = 1;

    cudaLaunchConfig_t cfg = {};
    cfg.gridDim  = dim3(DM_BLOCKS, 1, 1);
    cfg.blockDim = dim3(DM_THREADS, 1, 1);
    cfg.attrs = attrs;
    cfg.numAttrs = 1;
    cudaLaunchKernelEx(&cfg, dilate_merged_kernel, inp, tgt, out);
}

// round 16
// speedup vs baseline: 1.2144x; 1.2144x over previous
#include <cuda_runtime.h>
#include <cstdint>

// Problem constants (B=2, C=1, D=128, H=256, W=256)
#define NVOL   2
#define DD     128
#define HH     256
#define WW     256
#define NB     (NVOL*DD*HH*WW)      // 16,777,216 voxels
#define WPR    (WW/32)              // 8 packed words per row
#define NWORDS (NVOL*DD*HH*WPR)     // 524,288 words (2 MB)
#define PW     10.0

// pass1: 4096 blocks x 256 thr = 1,048,576 threads -> 4 quads/thread
#define P1_BLOCKS  4096
#define P1_THREADS 256
#define P1_TOTAL   (P1_BLOCKS*P1_THREADS)

// dilation kernels: 8 outputs/thread -> 65,536 threads each
#define XY_THREADS 128
#define XY_BLOCKS  ((NWORDS / 8) / XY_THREADS)   // 512
#define DZ_THREADS 128
#define DZ_BLOCKS  ((NWORDS / 8) / DZ_THREADS)   // 512

// Scratch (allocation-free __device__ globals; zero-initialized at load)
__device__ unsigned int g_mask[NWORDS];
__device__ unsigned int g_tmp[NWORDS];
__device__ double g_base;      // sum |t-i| over all voxels
__device__ double g_corr;      // sum |t-i| over NOT-dilated voxels
__device__ unsigned int g_bcount;

// ---------------------------------------------------------------------------
// Pass 1: single streaming read of input+target (128 MB).
// Emits base = sum|t-i| and packed support mask (0 < t < 1).
// ---------------------------------------------------------------------------
__global__ void __launch_bounds__(P1_THREADS) pass1_kernel(
        const float4* __restrict__ inp,
        const float4* __restrict__ tgt) {
    int tid = blockIdx.x * blockDim.x + threadIdx.x;
    float base = 0.0f;

    float4 a[4], b[4];
    #pragma unroll
    for (int k = 0; k < 4; ++k) {
        int i = tid + k * P1_TOTAL;
        a[k] = __ldcs(inp + i);
        b[k] = __ldcs(tgt + i);
    }
    #pragma unroll
    for (int k = 0; k < 4; ++k) {
        int i = tid + k * P1_TOTAL;
        float dx = fabsf(b[k].x - a[k].x);
        float dy = fabsf(b[k].y - a[k].y);
        float dz = fabsf(b[k].z - a[k].z);
        float dw = fabsf(b[k].w - a[k].w);
        base += (dx + dy) + (dz + dw);

        unsigned nib =
            (unsigned)(b[k].x > 0.0f && b[k].x < 1.0f)
          | ((unsigned)(b[k].y > 0.0f && b[k].y < 1.0f) << 1)
          | ((unsigned)(b[k].z > 0.0f && b[k].z < 1.0f) << 2)
          | ((unsigned)(b[k].w > 0.0f && b[k].w < 1.0f) << 3);
        // 8 consecutive threads' nibbles -> one 32-bit word
        unsigned p  = nib | (__shfl_down_sync(0xFFFFFFFFu, nib, 1) << 4);
        unsigned p2 = p   | (__shfl_down_sync(0xFFFFFFFFu, p,   2) << 8);
        unsigned w  = p2  | (__shfl_down_sync(0xFFFFFFFFu, p2,  4) << 16);
        if ((threadIdx.x & 7) == 0) __stcg(&g_mask[i >> 3], w);
    }

    #pragma unroll
    for (int off = 16; off > 0; off >>= 1)
        base += __shfl_down_sync(0xFFFFFFFFu, base, off);
    __shared__ float ws[P1_THREADS / 32];
    int lane = threadIdx.x & 31, wid = threadIdx.x >> 5;
    if (lane == 0) ws[wid] = base;
    __syncthreads();
    if (wid == 0) {
        float s = (lane < P1_THREADS / 32) ? ws[lane] : 0.0f;
        #pragma unroll
        for (int off = 4; off > 0; off >>= 1)
            s += __shfl_down_sync(0xFFFFFFFFu, s, off);
        if (lane == 0) atomicAdd(&g_base, (double)s);
    }
}

// horizontal (x) dilation by +-3 bits across word boundaries
__device__ __forceinline__ unsigned hdil3(unsigned prev, unsigned cur, unsigned next) {
    unsigned r = cur;
    r |= __funnelshift_l(prev, cur, 1);
    r |= __funnelshift_l(prev, cur, 2);
    r |= __funnelshift_l(prev, cur, 3);
    r |= __funnelshift_r(cur, next, 1);
    r |= __funnelshift_r(cur, next, 2);
    r |= __funnelshift_r(cur, next, 3);
    return r;
}

// sliding OR of width 7 over win[0..13] -> out[0..7] using suffix/prefix split
__device__ __forceinline__ void slide_or7(const unsigned* win, unsigned* out) {
    unsigned suf[7], pre[7];
    suf[6] = win[6];
    #pragma unroll
    for (int i = 5; i >= 0; --i) suf[i] = win[i] | suf[i + 1];
    pre[0] = win[7];
    #pragma unroll
    for (int j = 1; j < 7; ++j) pre[j] = pre[j - 1] | win[7 + j];
    out[0] = suf[0];
    #pragma unroll
    for (int k = 1; k < 7; ++k) out[k] = suf[k] | pre[k - 1];
    out[7] = pre[6];                     // window lies entirely in prefix side
}

// ---------------------------------------------------------------------------
// x+y dilation, 8 y-outputs per thread. g_mask -> g_tmp.
// Neighbor words (wx +- 1) come from adjacent lanes via shfl (1 load/row
// instead of 3). Loads are predicated (not branched) so shfl stays uniform.
// wx is the fastest-varying thread index -> fully coalesced loads/stores
// (the property every failed fusion attempt broke).
// ---------------------------------------------------------------------------
__global__ void __launch_bounds__(XY_THREADS) dilate_xy_kernel() {
    cudaGridDependencySynchronize();     // PDL: wait for pass1 completion
    int t = blockIdx.x * blockDim.x + threadIdx.x;    // 65536 threads
    int wx = t & 7;
    int yg = (t >> 3) & 31;                           // 32 groups of 8 rows
    int vz = t >> 8;                                  // v*DD+z, 0..255
    int rowbase = vz << 11;
    int y0 = yg << 3;

    unsigned hr[14];
    #pragma unroll
    for (int r = 0; r < 14; ++r) {
        int yy = y0 - 3 + r;
        unsigned cur = ((unsigned)yy < HH) ? g_mask[rowbase + (yy << 3) + wx] : 0u;
        unsigned prev = __shfl_up_sync(0xFFFFFFFFu, cur, 1);
        unsigned next = __shfl_down_sync(0xFFFFFFFFu, cur, 1);
        if (wx == 0) prev = 0u;
        if (wx == 7) next = 0u;
        hr[r] = hdil3(prev, cur, next);
    }
    unsigned outw[8];
    slide_or7(hr, outw);
    #pragma unroll
    for (int k = 0; k < 8; ++k)
        __stcg(&g_tmp[rowbase + ((y0 + k) << 3) + wx], outw[k]);
}

// ---------------------------------------------------------------------------
// Fused z-dilation (8 z-outputs/thread) + complement correction + finalize.
//   loss = 11*base - 10*corr ; out = loss/NB written by the last block.
// ---------------------------------------------------------------------------
__global__ void __launch_bounds__(DZ_THREADS) dilate_z_corr_kernel(
        const float* __restrict__ inp,
        const float* __restrict__ tgt,
        float* __restrict__ out) {
    cudaGridDependencySynchronize();     // PDL: wait for dilate_xy completion
    int t = blockIdx.x * blockDim.x + threadIdx.x;    // 65536 threads
    int wxy = t & 2047;                               // word within z-slice
    int zg  = (t >> 11) & 15;                         // 16 groups of 8 z
    int v   = t >> 15;
    int z0  = zg << 3;

    unsigned c[14];
    #pragma unroll
    for (int r = 0; r < 14; ++r) {
        int zz = z0 - 3 + r;
        c[r] = ((unsigned)zz < DD) ? g_tmp[(((v << 7) + zz) << 11) + wxy] : 0u;
    }
    unsigned res[8];
    slide_or7(c, res);

    float corr = 0.0f;
    #pragma unroll
    for (int k = 0; k < 8; ++k) {
        unsigned miss = ~res[k];                      // unweighted voxels
        if (miss) {
            int wordidx = (((v << 7) + (z0 + k)) << 11) + wxy;
            int vox0 = wordidx << 5;
            do {
                int bit = __ffs(miss) - 1;
                miss &= miss - 1u;
                int i = vox0 + bit;
                corr += fabsf(tgt[i] - inp[i]);
            } while (miss);
        }
    }

    #pragma unroll
    for (int off = 16; off > 0; off >>= 1)
        corr += __shfl_down_sync(0xFFFFFFFFu, corr, off);
    __shared__ float ws[DZ_THREADS / 32];
    int lane = threadIdx.x & 31, wid = threadIdx.x >> 5;
    if (lane == 0) ws[wid] = corr;
    __syncthreads();
    if (wid == 0) {
        float s = (lane < DZ_THREADS / 32) ? ws[lane] : 0.0f;
        #pragma unroll
        for (int off = 2; off > 0; off >>= 1)
            s += __shfl_down_sync(0xFFFFFFFFu, s, off);
        if (lane == 0) {
            atomicAdd(&g_corr, (double)s);
            __threadfence();
            unsigned prev = atomicAdd(&g_bcount, 1u);
            if (prev == gridDim.x - 1) {
                double total = (1.0 + PW) * g_base - PW * g_corr;
                out[0] = (float)(total / (double)NB);
                g_base = 0.0;        // reset for next graph replay
                g_corr = 0.0;
                g_bcount = 0u;
            }
        }
    }
}

extern "C" void kernel_launch(void* const* d_in, const int* in_sizes, int n_in,
                              void* d_out, int out_size) {
    const float* inp = (const float*)d_in[0];
    const float* tgt = (const float*)d_in[1];
    float* out = (float*)d_out;

    pass1_kernel<<<P1_BLOCKS, P1_THREADS>>>((const float4*)inp, (const float4*)tgt);

    // Tail kernels with programmatic stream serialization: their launch/ramp
    // overlaps the predecessor; cudaGridDependencySynchronize() in-kernel
    // provides the data dependency. Default (kernel-end) trigger on the
    // predecessor — early trigger measured harmful for the BW-bound pass1
    // (R13: 24.3 -> 28.6 us). Execution-level fusion of the tail measured
    // harmful 4x (R6/R10/R13/R15).
    cudaLaunchAttribute attrs[1];
    attrs[0].id = cudaLaunchAttributeProgrammaticStreamSerialization;
    attrs[0].val.programmaticStreamSerializationAllowed = 1;

    {
        cudaLaunchConfig_t cfg = {};
        cfg.gridDim  = dim3(XY_BLOCKS, 1, 1);
        cfg.blockDim = dim3(XY_THREADS, 1, 1);
        cfg.attrs = attrs;
        cfg.numAttrs = 1;
        cudaLaunchKernelEx(&cfg, dilate_xy_kernel);
    }
    {
        cudaLaunchConfig_t cfg = {};
        cfg.gridDim  = dim3(DZ_BLOCKS, 1, 1);
        cfg.blockDim = dim3(DZ_THREADS, 1, 1);
        cfg.attrs = attrs;
        cfg.numAttrs = 1;
        cudaLaunchKernelEx(&cfg, dilate_z_corr_kernel, inp, tgt, out);
    }
}